// round 5
// baseline (speedup 1.0000x reference)
#include <cuda_runtime.h>
#include <math.h>

#define GAMMA_F 0.99f
#define TAU 64          // tau == tauP == 64
#define BPB 32          // batch elements per block (= lanes)
#define THREADS 1024    // 32 warps
#define NW (THREADS / 32)
#define TPT (TAU * BPB / THREADS)   // taus per thread = 2

// Gather: warp -> tau, lane -> b  => each LDG touches ONE 2MB page,
// 32 lines inside a 32KB window. Results transposed into smem [t][b].
// Compute: thread = (b = lane, 2 taus); tp-loop over shared targets.
__global__ void __launch_bounds__(THREADS)
iqn_td_fused_kernel(const float* __restrict__ q,          // (tau, B, N)
                    const float* __restrict__ next_n_q,   // (tauP, B, N)
                    const int*   __restrict__ action,     // (B,)
                    const int*   __restrict__ next_action,// (B,)
                    const float* __restrict__ reward,     // (T, B)
                    const int*   __restrict__ done,       // (B,)
                    const float* __restrict__ replay_q,   // (tau, B)
                    const float* __restrict__ weight,     // (B,)
                    float* __restrict__ out,              // out[0]=loss, out[1..B]=td
                    int B, int N, int T, float gamma_T)
{
    const int tid  = threadIdx.x;
    const int lane = tid & 31;           // b_local
    const int w    = tid >> 5;           // warp id 0..31
    const int b0   = blockIdx.x * BPB;

    __shared__ float s_qsa[TAU][BPB];    // q_s_a transposed  [t][b]
    __shared__ float s_tgt[TAU][BPB];    // bellman target    [tp][b]
    __shared__ int   s_a[BPB], s_an[BPB];
    __shared__ float s_rsum[BPB], s_coef[BPB];
    __shared__ float s_red[NW][BPB];     // [32][32]

    // ---- prelude: per-b scalars (first warp) ----
    if (tid < BPB) {
        const int b = b0 + tid;
        s_a[tid]  = action[b];
        s_an[tid] = next_action[b];
        float r_sum = 0.0f, g = 1.0f;
        for (int tt = 0; tt < T; ++tt) {
            r_sum = fmaf(g, reward[tt * B + b], r_sum);
            g *= GAMMA_F;
        }
        s_rsum[tid] = r_sum;
        s_coef[tid] = (done[b] != 0) ? 0.0f : gamma_T;
    }
    __syncthreads();

    // ---- gather phase: page-local LDGs, warp w covers taus {w, w+32} ----
    {
        const int   a    = s_a[lane];
        const int   an   = s_an[lane];
        const float rsum = s_rsum[lane];
        const float coef = s_coef[lane];
        const size_t plane = (size_t)B * (size_t)N;
        const size_t rowb  = (size_t)(b0 + lane) * (size_t)N;

        #pragma unroll
        for (int k = 0; k < TAU / NW; ++k) {          // 2 iters
            const int t = w + k * NW;
            const size_t base = (size_t)t * plane + rowb;
            s_qsa[t][lane] = q[base + a];
            s_tgt[t][lane] = fmaf(coef, next_n_q[base + an], rsum);
        }
    }
    __syncthreads();

    // ---- compute phase: thread = (b=lane, taus = w*TPT .. ) ----
    const int tb = w * TPT;
    float qsa[TPT], rq[TPT], rq1[TPT], acc[TPT];
    #pragma unroll
    for (int j = 0; j < TPT; ++j) {
        qsa[j] = s_qsa[tb + j][lane];
        rq[j]  = replay_q[(tb + j) * B + b0 + lane];  // coalesced LDG (L2-hot)
        rq1[j] = 1.0f - rq[j];
        acc[j] = 0.0f;
    }

    // kappa=1: c=min(|u|,1); h = c*(0.5c-1)+|u|; f = (u<0)?(1-rq):rq
    #pragma unroll 8
    for (int tp = 0; tp < TAU; ++tp) {
        const float tgt = s_tgt[tp][lane];            // conflict-free LDS
        #pragma unroll
        for (int j = 0; j < TPT; ++j) {
            const float u  = tgt - qsa[j];
            const float au = fabsf(u);
            const float c  = fminf(au, 1.0f);
            const float h  = fmaf(c, fmaf(0.5f, c, -1.0f), au);
            acc[j] = fmaf((u < 0.0f) ? rq1[j] : rq[j], h, acc[j]);
        }
    }

    // ---- reduce: per-thread tau partials -> across the 32 warps per b ----
    float part = acc[0];
    #pragma unroll
    for (int j = 1; j < TPT; ++j) part += acc[j];
    s_red[w][lane] = part;
    __syncthreads();

    if (tid < BPB) {
        const int b = b0 + tid;
        float tot = 0.0f;
        #pragma unroll
        for (int k = 0; k < NW; ++k)
            tot += s_red[k][tid];
        const float td = tot * (1.0f / (float)TAU);   // mean over tauP
        out[1 + b] = td;                              // coalesced store
        float wsum = td * weight[b];
        #pragma unroll
        for (int off = 16; off > 0; off >>= 1)
            wsum += __shfl_down_sync(0xffffffffu, wsum, off);
        if (tid == 0)
            atomicAdd(out, wsum * (1.0f / (float)B)); // one atomic per block
    }
}

extern "C" void kernel_launch(void* const* d_in, const int* in_sizes, int n_in,
                              void* d_out, int out_size)
{
    const float* q        = (const float*)d_in[0];
    const float* next_n_q = (const float*)d_in[1];
    const int*   action   = (const int*)  d_in[2];
    const int*   naction  = (const int*)  d_in[3];
    const float* reward   = (const float*)d_in[4];
    const int*   done     = (const int*)  d_in[5];
    const float* replay_q = (const float*)d_in[6];
    const float* weight   = (const float*)d_in[7];

    const int B   = in_sizes[2];
    const int tau = in_sizes[6] / B;
    const int N   = in_sizes[0] / (tau * B);
    const int T   = in_sizes[4] / B;

    float gamma_T = 1.0f;
    for (int i = 0; i < T; ++i) gamma_T *= GAMMA_F;

    float* out = (float*)d_out;

    cudaMemsetAsync(out, 0, sizeof(float), 0);   // zero loss accumulator

    iqn_td_fused_kernel<<<B / BPB, THREADS>>>(q, next_n_q, action, naction,
                                              reward, done, replay_q, weight,
                                              out, B, N, T, gamma_T);
}

// round 6
// speedup vs baseline: 1.1400x; 1.1400x over previous
#include <cuda_runtime.h>
#include <math.h>

#define GAMMA_F 0.99f
#define TAU 64          // tau == tauP == 64
#define BPB 8           // batch elements per block
#define THREADS 256     // 8 warps
#define NW (THREADS / 32)
#define TPT (TAU * BPB / THREADS)   // taus per thread = 2

// Small CTAs (grid = B/8 = 512) so 3-4 CTAs co-reside per SM and the
// gather / compute phases of different CTAs overlap (latency hiding).
// Gather: lane -> (tau_sub, b_local): page-local, <=4 pages per warp-instr.
// Compute: thread = (b = tid&7, 2 taus); tp-loop over shared targets.
__global__ void __launch_bounds__(THREADS)
iqn_td_fused_kernel(const float* __restrict__ q,          // (tau, B, N)
                    const float* __restrict__ next_n_q,   // (tauP, B, N)
                    const int*   __restrict__ action,     // (B,)
                    const int*   __restrict__ next_action,// (B,)
                    const float* __restrict__ reward,     // (T, B)
                    const int*   __restrict__ done,       // (B,)
                    const float* __restrict__ replay_q,   // (tau, B)
                    const float* __restrict__ weight,     // (B,)
                    float* __restrict__ out,              // out[0]=loss, out[1..B]=td
                    int B, int N, int T, float gamma_T)
{
    const int tid  = threadIdx.x;
    const int lane = tid & 31;
    const int w    = tid >> 5;           // warp 0..7
    const int b0   = blockIdx.x * BPB;

    __shared__ float s_qsa[TAU][BPB];    // [t][b]
    __shared__ float s_tgt[TAU][BPB];    // [tp][b]
    __shared__ int   s_a[BPB], s_an[BPB];
    __shared__ float s_rsum[BPB], s_coef[BPB];
    __shared__ float s_red[NW][BPB];     // [8][8]

    // ---- prelude: per-b scalars ----
    if (tid < BPB) {
        const int b = b0 + tid;
        s_a[tid]  = action[b];
        s_an[tid] = next_action[b];
        float r_sum = 0.0f, g = 1.0f;
        for (int tt = 0; tt < T; ++tt) {
            r_sum = fmaf(g, reward[tt * B + b], r_sum);
            g *= GAMMA_F;
        }
        s_rsum[tid] = r_sum;
        s_coef[tid] = (done[b] != 0) ? 0.0f : gamma_T;
    }
    __syncthreads();

    // ---- gather: lane = (ts, bl); warp covers 4 taus x 8 b per pass ----
    {
        const int bl = lane & 7;
        const int ts = lane >> 3;        // 0..3
        const int   a    = s_a[bl];
        const int   an   = s_an[bl];
        const float rsum = s_rsum[bl];
        const float coef = s_coef[bl];
        const size_t plane = (size_t)B * (size_t)N;
        const size_t rowb  = (size_t)(b0 + bl) * (size_t)N;

        #pragma unroll
        for (int k = 0; k < 2; ++k) {    // taus: k*32 + w*4 + ts
            const int t = k * 32 + w * 4 + ts;
            const size_t base = (size_t)t * plane + rowb;
            s_qsa[t][bl] = q[base + a];
            s_tgt[t][bl] = fmaf(coef, next_n_q[base + an], rsum);
        }
    }
    __syncthreads();

    // ---- compute: thread = (b = tid&7, taus = (tid>>3)*2 .. +1) ----
    const int bl = tid & 7;
    const int tb = (tid >> 3) * TPT;
    float qsa[TPT], rq[TPT], rq1[TPT], acc[TPT];
    #pragma unroll
    for (int j = 0; j < TPT; ++j) {
        qsa[j] = s_qsa[tb + j][bl];
        rq[j]  = replay_q[(tb + j) * B + b0 + bl];
        rq1[j] = 1.0f - rq[j];
        acc[j] = 0.0f;
    }

    // kappa=1: c=min(|u|,1); h = c*(0.5c-1)+|u|; f = (u<0)?(1-rq):rq
    #pragma unroll 16
    for (int tp = 0; tp < TAU; ++tp) {
        const float tgt = s_tgt[tp][bl];          // broadcast LDS, conflict-free
        #pragma unroll
        for (int j = 0; j < TPT; ++j) {
            const float u  = tgt - qsa[j];
            const float au = fabsf(u);
            const float c  = fminf(au, 1.0f);
            const float h  = fmaf(c, fmaf(0.5f, c, -1.0f), au);
            acc[j] = fmaf((u < 0.0f) ? rq1[j] : rq[j], h, acc[j]);
        }
    }

    // ---- reduce: within warp over the 4 tau-groups sharing each bl ----
    float part = acc[0];
    #pragma unroll
    for (int j = 1; j < TPT; ++j) part += acc[j];
    part += __shfl_down_sync(0xffffffffu, part, 16);
    part += __shfl_down_sync(0xffffffffu, part, 8);
    if (lane < 8) s_red[w][lane] = part;          // per-warp per-b partial
    __syncthreads();

    if (tid < BPB) {
        const int b = b0 + tid;
        float tot = 0.0f;
        #pragma unroll
        for (int k = 0; k < NW; ++k)
            tot += s_red[k][tid];
        const float td = tot * (1.0f / (float)TAU);   // mean over tauP
        out[1 + b] = td;
        float wsum = td * weight[b];
        wsum += __shfl_down_sync(0x000000ffu, wsum, 4);
        wsum += __shfl_down_sync(0x000000ffu, wsum, 2);
        wsum += __shfl_down_sync(0x000000ffu, wsum, 1);
        if (tid == 0)
            atomicAdd(out, wsum * (1.0f / (float)B)); // one atomic per CTA
    }
}

extern "C" void kernel_launch(void* const* d_in, const int* in_sizes, int n_in,
                              void* d_out, int out_size)
{
    const float* q        = (const float*)d_in[0];
    const float* next_n_q = (const float*)d_in[1];
    const int*   action   = (const int*)  d_in[2];
    const int*   naction  = (const int*)  d_in[3];
    const float* reward   = (const float*)d_in[4];
    const int*   done     = (const int*)  d_in[5];
    const float* replay_q = (const float*)d_in[6];
    const float* weight   = (const float*)d_in[7];

    const int B   = in_sizes[2];
    const int tau = in_sizes[6] / B;
    const int N   = in_sizes[0] / (tau * B);
    const int T   = in_sizes[4] / B;

    float gamma_T = 1.0f;
    for (int i = 0; i < T; ++i) gamma_T *= GAMMA_F;

    float* out = (float*)d_out;

    cudaMemsetAsync(out, 0, sizeof(float), 0);   // zero loss accumulator

    iqn_td_fused_kernel<<<B / BPB, THREADS>>>(q, next_n_q, action, naction,
                                              reward, done, replay_q, weight,
                                              out, B, N, T, gamma_T);
}